// round 12
// baseline (speedup 1.0000x reference)
#include <cuda_runtime.h>
#include <cuda_bf16.h>
#include <math.h>
#include <stdint.h>

// NT-Xent loss. B=4096, D=512. Single persistent kernel (148 CTAs):
// normalize -> barrier -> symmetric fused bf16 HMMA sim-GEMM (pipelined
// epilogue) -> barrier -> loss -> barrier -> mean. Counters zeroed per
// launch via cudaMemsetAsync graph node.

#define D 512
#define MAXN 8192
#define TEMP_INV 2.0f
#define QSCALE 1.6986436f   // sqrt(2 * log2(e))
#define NCTA 148
#define NB 64
#define NTILES 2080

#define TM 128
#define KCHUNK 128

#define SA_OFF 0
#define SA_BYTES (TM * D * 2)
#define SB_OFF SA_BYTES
#define SB_BYTES (TM * KCHUNK * 2)
#define NSTAGE 3
#define SRED_OFF (SB_OFF + NSTAGE * SB_BYTES)
#define SMEM_TOTAL (SRED_OFF + 2048)

#define NZR (NB * 33 * 128)
#define NWARPS_TOT (NCTA * 8)

__device__ __nv_bfloat16 g_znb[(size_t)MAXN * D];
__device__ float g_pos[MAXN / 2];
__device__ float g_rs[NZR];
__device__ float g_cs[NZR];
__device__ float g_bpart[NCTA];
__device__ unsigned int g_sync[8];   // [0..2] counters, [4..6] flags

__device__ __forceinline__ uint32_t smem_u32(const void* p) {
    uint32_t a;
    asm("{ .reg .u64 t; cvta.to.shared.u64 t, %1; cvt.u32.u64 %0, t; }" : "=r"(a) : "l"(p));
    return a;
}
__device__ __forceinline__ float ex2f(float x) {
    float r;
    asm("ex2.approx.f32 %0, %1;" : "=f"(r) : "f"(x));
    return r;
}
__device__ __forceinline__ void ldsm4(uint32_t* r, uint32_t addr) {
    asm volatile("ldmatrix.sync.aligned.m8n8.x4.shared.b16 {%0,%1,%2,%3}, [%4];"
                 : "=r"(r[0]), "=r"(r[1]), "=r"(r[2]), "=r"(r[3]) : "r"(addr));
}
__device__ __forceinline__ void mma_bf16(float* c, const uint32_t* a, const uint32_t* b) {
    asm volatile(
        "mma.sync.aligned.m16n8k16.row.col.f32.bf16.bf16.f32 "
        "{%0,%1,%2,%3}, {%4,%5,%6,%7}, {%8,%9}, {%0,%1,%2,%3};"
        : "+f"(c[0]), "+f"(c[1]), "+f"(c[2]), "+f"(c[3])
        : "r"(a[0]), "r"(a[1]), "r"(a[2]), "r"(a[3]), "r"(b[0]), "r"(b[1]));
}
__device__ __forceinline__ void tmap(int t, int& r, int& off, int& c) {
    if (t < 32 * 33) { r = t / 33; off = t - r * 33; }
    else { int u = t - 32 * 33; r = 32 + u / 32; off = u - (u / 32) * 32; }
    c = (r + off) & 63;
}

// device-wide barrier: all NCTA CTAs co-resident (grid == #SMs, occ 1)
__device__ __forceinline__ void gbar(int slot) {
    __syncthreads();
    if (threadIdx.x == 0) {
        __threadfence();
        unsigned old = atomicAdd(&g_sync[slot], 1u);
        if (old == NCTA - 1) {
            atomicExch(&g_sync[slot + 4], 1u);
        } else {
            while (atomicAdd(&g_sync[slot + 4], 0u) == 0u) {}
        }
        __threadfence();
    }
    __syncthreads();
}

// ---------------- denom helpers (unchanged from R11) ----------------
__device__ __forceinline__ void prefetchB(const __nv_bfloat16* __restrict__ znb,
                                          int colBase, int kc, uint32_t smemBuf, int tid) {
#pragma unroll
    for (int i = 0; i < 8; i++) {
        int idx = tid + i * 256;
        int n = idx >> 4;
        int c = idx & 15;
        const void* g = znb + (size_t)(colBase + n) * D + kc * KCHUNK + c * 8;
        uint32_t s = smemBuf + n * 256 + ((c ^ (n & 7)) << 4);
        asm volatile("cp.async.cg.shared.global [%0], [%1], 16;" :: "r"(s), "l"(g));
    }
    asm volatile("cp.async.commit_group;");
}
__device__ __forceinline__ void loadA(const __nv_bfloat16* __restrict__ znb,
                                      int rowBase, uint32_t sA, int tid) {
#pragma unroll 8
    for (int idx = tid; idx < TM * 64; idx += 256) {
        int r = idx >> 6;
        int c = idx & 63;
        const void* g = znb + (size_t)(rowBase + r) * D + c * 8;
        uint32_t s = sA + r * 1024 + ((c ^ (r & 7)) << 4);
        asm volatile("cp.async.cg.shared.global [%0], [%1], 16;" :: "r"(s), "l"(g));
    }
    asm volatile("cp.async.commit_group;");
}

__device__ __forceinline__ void emit_rows(float rowp[2][2], int r, int offFirst,
                                          float* scratch, int tid, int lane,
                                          int warpM, int warpN) {
    __syncthreads();
#pragma unroll
    for (int mt = 0; mt < 2; mt++)
#pragma unroll
        for (int h = 0; h < 2; h++) {
            float p = rowp[mt][h];
            p += __shfl_xor_sync(0xffffffffu, p, 1);
            p += __shfl_xor_sync(0xffffffffu, p, 2);
            rowp[mt][h] = p;
        }
    if ((lane & 3) == 0) {
#pragma unroll
        for (int mt = 0; mt < 2; mt++)
#pragma unroll
            for (int h = 0; h < 2; h++) {
                int rl = warpM * 32 + mt * 16 + (lane >> 2) + 8 * h;
                scratch[rl * 2 + warpN] = rowp[mt][h];
            }
    }
    __syncthreads();
    if (tid < TM)
        g_rs[(r * 33 + offFirst) * 128 + tid] = scratch[tid * 2] + scratch[tid * 2 + 1];
}

__device__ __forceinline__ void stale_groups(int g0, float (&st)[2][8][4],
                                             float (&rowp)[2][2], float (&colp)[8][2],
                                             int staleOff, int staleColW, int staleR0) {
    if (staleOff == 0) {
#pragma unroll
        for (int u = 0; u < 4; u++) {
            const int g = g0 + u;
            const int mt = g >> 3, nt = g & 7;
            int r0 = staleR0 + mt * 16, r1 = r0 + 8;
            int c0 = staleColW + nt * 8;
            float e0 = ex2f(st[mt][nt][0]);
            float e1 = ex2f(st[mt][nt][1]);
            float e2 = ex2f(st[mt][nt][2]);
            float e3 = ex2f(st[mt][nt][3]);
            rowp[mt][0] += (c0 != r0 ? e0 : 0.f) + (c0 + 1 != r0 ? e1 : 0.f);
            rowp[mt][1] += (c0 != r1 ? e2 : 0.f) + (c0 + 1 != r1 ? e3 : 0.f);
            st[mt][nt][0] = 0.f; st[mt][nt][1] = 0.f;
            st[mt][nt][2] = 0.f; st[mt][nt][3] = 0.f;
        }
    } else {
#pragma unroll
        for (int u = 0; u < 4; u++) {
            const int g = g0 + u;
            const int mt = g >> 3, nt = g & 7;
            float e0 = ex2f(st[mt][nt][0]);
            float e1 = ex2f(st[mt][nt][1]);
            float e2 = ex2f(st[mt][nt][2]);
            float e3 = ex2f(st[mt][nt][3]);
            rowp[mt][0] += e0 + e1;
            rowp[mt][1] += e2 + e3;
            colp[nt][0] += e0 + e2;
            colp[nt][1] += e1 + e3;
            st[mt][nt][0] = 0.f; st[mt][nt][1] = 0.f;
            st[mt][nt][2] = 0.f; st[mt][nt][3] = 0.f;
        }
    }
}

__device__ __forceinline__ void colp_finalize(float (&colp)[8][2], int staleR, int staleOff,
                                              float* scratch, int tid, int lane,
                                              int warpM, int warpN) {
    __syncthreads();
#pragma unroll
    for (int nt = 0; nt < 8; nt++)
#pragma unroll
        for (int q = 0; q < 2; q++) {
            float p = colp[nt][q];
            p += __shfl_xor_sync(0xffffffffu, p, 4);
            p += __shfl_xor_sync(0xffffffffu, p, 8);
            p += __shfl_xor_sync(0xffffffffu, p, 16);
            colp[nt][q] = p;
        }
    if (lane < 4) {
#pragma unroll
        for (int nt = 0; nt < 8; nt++)
#pragma unroll
            for (int q = 0; q < 2; q++)
                scratch[(warpN * 4 + warpM) * 64 + nt * 8 + lane * 2 + q] = colp[nt][q];
    }
    __syncthreads();
    if (tid < TM) {
        int wn = tid >> 6, cl = tid & 63;
        float s = scratch[(wn * 4 + 0) * 64 + cl] + scratch[(wn * 4 + 1) * 64 + cl]
                + scratch[(wn * 4 + 2) * 64 + cl] + scratch[(wn * 4 + 3) * 64 + cl];
        g_cs[(staleR * 33 + staleOff) * 128 + tid] = s;
    }
#pragma unroll
    for (int nt = 0; nt < 8; nt++) { colp[nt][0] = 0.f; colp[nt][1] = 0.f; }
}

__device__ __forceinline__ void flush_stale(float (&st)[2][8][4], float (&rowp)[2][2],
                                            float (&colp)[8][2], int staleOff, int staleColW,
                                            int staleR0, int staleR, float* scratch,
                                            int tid, int lane, int warpM, int warpN) {
    stale_groups(0, st, rowp, colp, staleOff, staleColW, staleR0);
    stale_groups(4, st, rowp, colp, staleOff, staleColW, staleR0);
    stale_groups(8, st, rowp, colp, staleOff, staleColW, staleR0);
    stale_groups(12, st, rowp, colp, staleOff, staleColW, staleR0);
    if (staleOff > 0)
        colp_finalize(colp, staleR, staleOff, scratch, tid, lane, warpM, warpN);
}

__device__ __forceinline__ void tile_body(
    float (&cur)[2][8][4], float (&st)[2][8][4],
    float (&rowp)[2][2], float (&colp)[8][2],
    int tIdx, int istart, int nIts,
    int staleOff, int staleColW, int staleR0,
    const __nv_bfloat16* __restrict__ znb,
    uint32_t sB, uint32_t aBase, int aXor, int aC,
    int bRow, int bXor, int bC, int tid)
{
#pragma unroll
    for (int kc = 0; kc < 4; ++kc) {
        const int git = (tIdx - istart) * 4 + kc;
        asm volatile("cp.async.wait_group 1;");
        __syncthreads();
        if (git + 2 < nIts) {
            int r2, o2, c2;
            tmap(istart + ((git + 2) >> 2), r2, o2, c2);
            prefetchB(znb, c2 * TM, (git + 2) & 3, sB + ((git + 2) % 3) * SB_BYTES, tid);
        } else {
            asm volatile("cp.async.commit_group;");
        }
        const uint32_t bufB = sB + (git % 3) * SB_BYTES;
#pragma unroll
        for (int s = 0; s < 8; ++s) {
            uint32_t af[2][4];
#pragma unroll
            for (int mt = 0; mt < 2; mt++)
                ldsm4(af[mt], aBase + mt * 16384 + (((kc * 16 + s * 2 + aC) ^ aXor) << 4));
#pragma unroll
            for (int bg = 0; bg < 4; bg++) {
                uint32_t bf[4];
                ldsm4(bf, bufB + (bRow + bg * 16) * 256 + (((s * 2 + bC) ^ bXor) << 4));
#pragma unroll
                for (int mt = 0; mt < 2; mt++) {
                    mma_bf16(cur[mt][bg * 2], af[mt], bf);
                    mma_bf16(cur[mt][bg * 2 + 1], af[mt], bf + 2);
                }
            }
        }
        if (staleOff >= 0)
            stale_groups(kc * 4, st, rowp, colp, staleOff, staleColW, staleR0);
    }
}

// ---------------------------------------------------------------------------
// Fused persistent kernel
// ---------------------------------------------------------------------------
__global__ void __launch_bounds__(256, 1) fused_kernel(
    const float* __restrict__ zi, const float* __restrict__ zj,
    float* __restrict__ out, int B)
{
    extern __shared__ char smem[];
    const int tid = threadIdx.x;
    const int lane = tid & 31;
    const int wid = tid >> 5;
    const int warpM = wid & 3;
    const int warpN = wid >> 2;
    const int cta = blockIdx.x;
    const int N = 2 * B;

    // ===== Phase 1: normalize (warp per pair, grid-stride) =====
    for (int row = cta * 8 + wid; row < B; row += NWARPS_TOT) {
        float4 vi[4], vj[4];
        const float4* pi = (const float4*)(zi + (size_t)row * D);
        const float4* pj = (const float4*)(zj + (size_t)row * D);
#pragma unroll
        for (int q = 0; q < 4; q++) { vi[q] = pi[q * 32 + lane]; vj[q] = pj[q * 32 + lane]; }
        float ssi = 0.f, ssj = 0.f, dij = 0.f;
#pragma unroll
        for (int q = 0; q < 4; q++) {
            ssi += vi[q].x * vi[q].x + vi[q].y * vi[q].y + vi[q].z * vi[q].z + vi[q].w * vi[q].w;
            ssj += vj[q].x * vj[q].x + vj[q].y * vj[q].y + vj[q].z * vj[q].z + vj[q].w * vj[q].w;
            dij += vi[q].x * vj[q].x + vi[q].y * vj[q].y + vi[q].z * vj[q].z + vi[q].w * vj[q].w;
        }
#pragma unroll
        for (int o = 16; o > 0; o >>= 1) {
            ssi += __shfl_xor_sync(0xffffffffu, ssi, o);
            ssj += __shfl_xor_sync(0xffffffffu, ssj, o);
            dij += __shfl_xor_sync(0xffffffffu, dij, o);
        }
        float ri = rsqrtf(ssi), rj = rsqrtf(ssj);
        float sci = ri * QSCALE, scj = rj * QSCALE;
        __nv_bfloat16* oi = g_znb + (size_t)row * D;
        __nv_bfloat16* oj = g_znb + (size_t)(row + B) * D;
#pragma unroll
        for (int q = 0; q < 4; q++) {
            int e = (q * 32 + lane) * 4;
            __nv_bfloat162 a0 = __floats2bfloat162_rn(vi[q].x * sci, vi[q].y * sci);
            __nv_bfloat162 a1 = __floats2bfloat162_rn(vi[q].z * sci, vi[q].w * sci);
            *(__nv_bfloat162*)(oi + e) = a0;
            *(__nv_bfloat162*)(oi + e + 2) = a1;
            __nv_bfloat162 b0 = __floats2bfloat162_rn(vj[q].x * scj, vj[q].y * scj);
            __nv_bfloat162 b1 = __floats2bfloat162_rn(vj[q].z * scj, vj[q].w * scj);
            *(__nv_bfloat162*)(oj + e) = b0;
            *(__nv_bfloat162*)(oj + e + 2) = b1;
        }
        if (lane == 0) g_pos[row] = dij * ri * rj * TEMP_INV;
    }
    for (int i = cta * 256 + tid; i < NZR; i += NCTA * 256)
        g_rs[i] = 0.0f;

    gbar(0);

    // ===== Phase 2: denom (identical to R11) =====
    {
        const __nv_bfloat16* __restrict__ znb = g_znb;
        uint32_t sA = smem_u32(smem) + SA_OFF;
        uint32_t sB = smem_u32(smem) + SB_OFF;
        float* scratch = (float*)(smem + SRED_OFF);

        const int aRow = warpM * 32 + (lane & 15);
        const uint32_t aBase = sA + aRow * 1024;
        const int aXor = aRow & 7;
        const int aC = lane >> 4;
        const int bRow = warpN * 64 + (lane & 7) + ((lane >> 4) << 3);
        const int bXor = bRow & 7;
        const int bC = (lane >> 3) & 1;

        const int istart = (cta * NTILES) / NCTA;
        const int iend = ((cta + 1) * NTILES) / NCTA;
        const int nIts = (iend - istart) * 4;

        int rcur, offcur, ccur;
        tmap(istart, rcur, offcur, ccur);
        int rprev = rcur;
        int offFirst = offcur;

        loadA(znb, rcur * TM, sA, tid);
        asm volatile("cp.async.wait_group 0;");
        __syncthreads();
        prefetchB(znb, ccur * TM, 0, sB, tid);
        prefetchB(znb, ccur * TM, 1, sB + SB_BYTES, tid);

        float accA[2][8][4], accB[2][8][4];
#pragma unroll
        for (int mt = 0; mt < 2; mt++)
#pragma unroll
            for (int nt = 0; nt < 8; nt++)
#pragma unroll
                for (int j = 0; j < 4; j++) { accA[mt][nt][j] = 0.f; accB[mt][nt][j] = 0.f; }
        float rowp[2][2] = {{0.f, 0.f}, {0.f, 0.f}};
        float colp[8][2];
#pragma unroll
        for (int nt = 0; nt < 8; nt++) { colp[nt][0] = 0.f; colp[nt][1] = 0.f; }

        int staleOff = -1, staleR = 0, staleColW = 0, staleR0 = 0;

        for (int t = istart; t < iend; ++t) {
            tmap(t, rcur, offcur, ccur);
            const int par = (t - istart) & 1;
            if (rcur != rprev) {
                if (staleOff >= 0) {
                    if (par == 0)
                        flush_stale(accB, rowp, colp, staleOff, staleColW, staleR0, staleR,
                                    scratch, tid, lane, warpM, warpN);
                    else
                        flush_stale(accA, rowp, colp, staleOff, staleColW, staleR0, staleR,
                                    scratch, tid, lane, warpM, warpN);
                    staleOff = -1;
                }
                emit_rows(rowp, rprev, offFirst, scratch, tid, lane, warpM, warpN);
                rowp[0][0] = rowp[0][1] = rowp[1][0] = rowp[1][1] = 0.f;
                offFirst = offcur;
                asm volatile("cp.async.wait_group 0;");
                __syncthreads();
                loadA(znb, rcur * TM, sA, tid);
                asm volatile("cp.async.wait_group 0;");
                __syncthreads();
                rprev = rcur;
            }

            if (par == 0)
                tile_body(accA, accB, rowp, colp, t, istart, nIts,
                          staleOff, staleColW, staleR0, znb, sB, aBase, aXor, aC,
                          bRow, bXor, bC, tid);
            else
                tile_body(accB, accA, rowp, colp, t, istart, nIts,
                          staleOff, staleColW, staleR0, znb, sB, aBase, aXor, aC,
                          bRow, bXor, bC, tid);

            if (staleOff > 0)
                colp_finalize(colp, staleR, staleOff, scratch, tid, lane, warpM, warpN);

            staleOff = offcur;
            staleR = rcur;
            staleColW = ccur * TM + warpN * 64 + (lane & 3) * 2;
            staleR0 = rcur * TM + warpM * 32 + (lane >> 2);
        }

        const int parEnd = (iend - istart) & 1;
        if (parEnd == 0)
            flush_stale(accB, rowp, colp, staleOff, staleColW, staleR0, staleR,
                        scratch, tid, lane, warpM, warpN);
        else
            flush_stale(accA, rowp, colp, staleOff, staleColW, staleR0, staleR,
                        scratch, tid, lane, warpM, warpN);
        emit_rows(rowp, rprev, offFirst, scratch, tid, lane, warpM, warpN);
    }

    gbar(1);

    // ===== Phase 3: loss (warp per row, grid-stride) =====
    float lsum = 0.f;
    for (int rowg = cta * 8 + wid; rowg < N; rowg += NWARPS_TOT) {
        int b = rowg >> 7, lr = rowg & 127;
        float d = g_rs[(b * 33 + lane) * 128 + lr];
        if (lane == 0 && b < 32) d += g_rs[(b * 33 + 32) * 128 + lr];
        {
            int off2 = lane + 1;
            int rr = (b - off2 + 64) & 63;
            if (off2 < 32 || rr < 32) d += g_cs[(rr * 33 + off2) * 128 + lr];
        }
#pragma unroll
        for (int o = 16; o > 0; o >>= 1) d += __shfl_xor_sync(0xffffffffu, d, o);
        if (lane == 0) {
            float pos = g_pos[(rowg < B) ? rowg : (rowg - B)];
            lsum += logf(d + 1e-8f) - pos;
        }
    }
    {
        float* scratch = (float*)(smem + SRED_OFF);
        __syncthreads();
        if (lane == 0) scratch[wid] = lsum;
        __syncthreads();
        if (tid == 0) {
            float s = 0.f;
#pragma unroll
            for (int i = 0; i < 8; i++) s += scratch[i];
            g_bpart[cta] = s;
        }
    }

    gbar(2);

    // ===== Phase 4: final mean (CTA 0, fixed order) =====
    if (cta == 0) {
        float* scratch = (float*)(smem + SRED_OFF);
        if (tid < NCTA) scratch[tid] = g_bpart[tid];
        __syncthreads();
        if (tid == 0) {
            float s = 0.f;
            for (int i = 0; i < NCTA; i++) s += scratch[i];
            out[0] = s / (float)N;
        }
    }
}

// ---------------------------------------------------------------------------
extern "C" void kernel_launch(void* const* d_in, const int* in_sizes, int n_in,
                              void* d_out, int out_size) {
    const float* zi = (const float*)d_in[0];
    const float* zj = (const float*)d_in[1];
    int B = in_sizes[0] / D;  // 4096

    cudaFuncSetAttribute(fused_kernel, cudaFuncAttributeMaxDynamicSharedMemorySize, SMEM_TOTAL);

    void* syncPtr = nullptr;
    cudaGetSymbolAddress(&syncPtr, g_sync);
    cudaMemsetAsync(syncPtr, 0, sizeof(unsigned int) * 8, 0);

    fused_kernel<<<NCTA, 256, SMEM_TOTAL>>>(zi, zj, (float*)d_out, B);
}

// round 14
// speedup vs baseline: 1.0634x; 1.0634x over previous
#include <cuda_runtime.h>
#include <cuda_bf16.h>
#include <math.h>
#include <stdint.h>

// NT-Xent loss. B=4096, D=512. Symmetric fused bf16 HMMA sim-GEMM.
// Mainloop: batched fragment loads per k16 step + stale-tile exp epilogue
// interleaved inside the s-loop (one stale_pair per s-point — R13 fix).

#define D 512
#define MAXN 8192
#define TEMP_INV 2.0f
#define QSCALE 1.6986436f   // sqrt(2 * log2(e))
#define NCTA 148
#define NB 64
#define NTILES 2080

#define TM 128
#define KCHUNK 128

#define SA_OFF 0
#define SA_BYTES (TM * D * 2)
#define SB_OFF SA_BYTES
#define SB_BYTES (TM * KCHUNK * 2)
#define NSTAGE 3
#define SRED_OFF (SB_OFF + NSTAGE * SB_BYTES)
#define SMEM_TOTAL (SRED_OFF + 2048)

#define NLBLK 1024
#define NZR (NB * 33 * 128)

__device__ __nv_bfloat16 g_znb[(size_t)MAXN * D];
__device__ float g_pos[MAXN / 2];
__device__ float g_rs[NZR];
__device__ float g_cs[NZR];
__device__ float g_bpart[NLBLK];
__device__ unsigned int g_ctr = 0;

__device__ __forceinline__ uint32_t smem_u32(const void* p) {
    uint32_t a;
    asm("{ .reg .u64 t; cvta.to.shared.u64 t, %1; cvt.u32.u64 %0, t; }" : "=r"(a) : "l"(p));
    return a;
}
__device__ __forceinline__ float ex2f(float x) {
    float r;
    asm("ex2.approx.f32 %0, %1;" : "=f"(r) : "f"(x));
    return r;
}
__device__ __forceinline__ void ldsm4(uint32_t* r, uint32_t addr) {
    asm volatile("ldmatrix.sync.aligned.m8n8.x4.shared.b16 {%0,%1,%2,%3}, [%4];"
                 : "=r"(r[0]), "=r"(r[1]), "=r"(r[2]), "=r"(r[3]) : "r"(addr));
}
__device__ __forceinline__ void mma_bf16(float* c, const uint32_t* a, const uint32_t* b) {
    asm volatile(
        "mma.sync.aligned.m16n8k16.row.col.f32.bf16.bf16.f32 "
        "{%0,%1,%2,%3}, {%4,%5,%6,%7}, {%8,%9}, {%0,%1,%2,%3};"
        : "+f"(c[0]), "+f"(c[1]), "+f"(c[2]), "+f"(c[3])
        : "r"(a[0]), "r"(a[1]), "r"(a[2]), "r"(a[3]), "r"(b[0]), "r"(b[1]));
}
__device__ __forceinline__ void tmap(int t, int& r, int& off, int& c) {
    if (t < 32 * 33) { r = t / 33; off = t - r * 33; }
    else { int u = t - 32 * 33; r = 32 + u / 32; off = u - (u / 32) * 32; }
    c = (r + off) & 63;
}

// ---------------------------------------------------------------------------
// 1) normalize: one warp per pair; no block sync. Also zeros g_rs.
// ---------------------------------------------------------------------------
__global__ void normalize_kernel(const float* __restrict__ zi,
                                 const float* __restrict__ zj, int B) {
    int lane = threadIdx.x & 31;
    int w = threadIdx.x >> 5;
    int row = blockIdx.x * 8 + w;

    float4 vi[4], vj[4];
    const float4* pi = (const float4*)(zi + (size_t)row * D);
    const float4* pj = (const float4*)(zj + (size_t)row * D);
#pragma unroll
    for (int q = 0; q < 4; q++) { vi[q] = pi[q * 32 + lane]; vj[q] = pj[q * 32 + lane]; }

    float ssi = 0.f, ssj = 0.f, dij = 0.f;
#pragma unroll
    for (int q = 0; q < 4; q++) {
        ssi += vi[q].x * vi[q].x + vi[q].y * vi[q].y + vi[q].z * vi[q].z + vi[q].w * vi[q].w;
        ssj += vj[q].x * vj[q].x + vj[q].y * vj[q].y + vj[q].z * vj[q].z + vj[q].w * vj[q].w;
        dij += vi[q].x * vj[q].x + vi[q].y * vj[q].y + vi[q].z * vj[q].z + vi[q].w * vj[q].w;
    }
#pragma unroll
    for (int o = 16; o > 0; o >>= 1) {
        ssi += __shfl_xor_sync(0xffffffffu, ssi, o);
        ssj += __shfl_xor_sync(0xffffffffu, ssj, o);
        dij += __shfl_xor_sync(0xffffffffu, dij, o);
    }
    float ri = rsqrtf(ssi), rj = rsqrtf(ssj);
    float sci = ri * QSCALE, scj = rj * QSCALE;

    __nv_bfloat16* oi = g_znb + (size_t)row * D;
    __nv_bfloat16* oj = g_znb + (size_t)(row + B) * D;
#pragma unroll
    for (int q = 0; q < 4; q++) {
        int e = (q * 32 + lane) * 4;
        __nv_bfloat162 a0 = __floats2bfloat162_rn(vi[q].x * sci, vi[q].y * sci);
        __nv_bfloat162 a1 = __floats2bfloat162_rn(vi[q].z * sci, vi[q].w * sci);
        *(__nv_bfloat162*)(oi + e) = a0;
        *(__nv_bfloat162*)(oi + e + 2) = a1;
        __nv_bfloat162 b0 = __floats2bfloat162_rn(vj[q].x * scj, vj[q].y * scj);
        __nv_bfloat162 b1 = __floats2bfloat162_rn(vj[q].z * scj, vj[q].w * scj);
        *(__nv_bfloat162*)(oj + e) = b0;
        *(__nv_bfloat162*)(oj + e + 2) = b1;
    }
    if (lane == 0) g_pos[row] = dij * ri * rj * TEMP_INV;
    for (int i = blockIdx.x * blockDim.x + threadIdx.x; i < NZR; i += gridDim.x * blockDim.x)
        g_rs[i] = 0.0f;
}

// ---------------------------------------------------------------------------
// 2) denom helpers
// ---------------------------------------------------------------------------
__device__ __forceinline__ void prefetchB(const __nv_bfloat16* __restrict__ znb,
                                          int colBase, int kc, uint32_t smemBuf, int tid) {
#pragma unroll
    for (int i = 0; i < 8; i++) {
        int idx = tid + i * 256;
        int n = idx >> 4;
        int c = idx & 15;
        const void* g = znb + (size_t)(colBase + n) * D + kc * KCHUNK + c * 8;
        uint32_t s = smemBuf + n * 256 + ((c ^ (n & 7)) << 4);
        asm volatile("cp.async.cg.shared.global [%0], [%1], 16;" :: "r"(s), "l"(g));
    }
    asm volatile("cp.async.commit_group;");
}
__device__ __forceinline__ void loadA(const __nv_bfloat16* __restrict__ znb,
                                      int rowBase, uint32_t sA, int tid) {
#pragma unroll 8
    for (int idx = tid; idx < TM * 64; idx += 256) {
        int r = idx >> 6;
        int c = idx & 63;
        const void* g = znb + (size_t)(rowBase + r) * D + c * 8;
        uint32_t s = sA + r * 1024 + ((c ^ (r & 7)) << 4);
        asm volatile("cp.async.cg.shared.global [%0], [%1], 16;" :: "r"(s), "l"(g));
    }
    asm volatile("cp.async.commit_group;");
}

__device__ __forceinline__ void emit_rows(float rowp[2][2], int r, int offFirst,
                                          float* scratch, int tid, int lane,
                                          int warpM, int warpN) {
    __syncthreads();
#pragma unroll
    for (int mt = 0; mt < 2; mt++)
#pragma unroll
        for (int h = 0; h < 2; h++) {
            float p = rowp[mt][h];
            p += __shfl_xor_sync(0xffffffffu, p, 1);
            p += __shfl_xor_sync(0xffffffffu, p, 2);
            rowp[mt][h] = p;
        }
    if ((lane & 3) == 0) {
#pragma unroll
        for (int mt = 0; mt < 2; mt++)
#pragma unroll
            for (int h = 0; h < 2; h++) {
                int rl = warpM * 32 + mt * 16 + (lane >> 2) + 8 * h;
                scratch[rl * 2 + warpN] = rowp[mt][h];
            }
    }
    __syncthreads();
    if (tid < TM)
        g_rs[(r * 33 + offFirst) * 128 + tid] = scratch[tid * 2] + scratch[tid * 2 + 1];
}

// process 2 epilogue groups [g0, g0+2) of the stale accumulator buffer
__device__ __forceinline__ void stale_pair(int g0, float (&st)[2][8][4],
                                           float (&rowp)[2][2], float (&colp)[8][2],
                                           int staleOff, int staleColW, int staleR0) {
    if (staleOff == 0) {
#pragma unroll
        for (int u = 0; u < 2; u++) {
            const int g = g0 + u;
            const int mt = g >> 3, nt = g & 7;
            int r0 = staleR0 + mt * 16, r1 = r0 + 8;
            int c0 = staleColW + nt * 8;
            float e0 = ex2f(st[mt][nt][0]);
            float e1 = ex2f(st[mt][nt][1]);
            float e2 = ex2f(st[mt][nt][2]);
            float e3 = ex2f(st[mt][nt][3]);
            rowp[mt][0] += (c0 != r0 ? e0 : 0.f) + (c0 + 1 != r0 ? e1 : 0.f);
            rowp[mt][1] += (c0 != r1 ? e2 : 0.f) + (c0 + 1 != r1 ? e3 : 0.f);
            st[mt][nt][0] = 0.f; st[mt][nt][1] = 0.f;
            st[mt][nt][2] = 0.f; st[mt][nt][3] = 0.f;
        }
    } else {
#pragma unroll
        for (int u = 0; u < 2; u++) {
            const int g = g0 + u;
            const int mt = g >> 3, nt = g & 7;
            float e0 = ex2f(st[mt][nt][0]);
            float e1 = ex2f(st[mt][nt][1]);
            float e2 = ex2f(st[mt][nt][2]);
            float e3 = ex2f(st[mt][nt][3]);
            rowp[mt][0] += e0 + e1;
            rowp[mt][1] += e2 + e3;
            colp[nt][0] += e0 + e2;
            colp[nt][1] += e1 + e3;
            st[mt][nt][0] = 0.f; st[mt][nt][1] = 0.f;
            st[mt][nt][2] = 0.f; st[mt][nt][3] = 0.f;
        }
    }
}

__device__ __forceinline__ void colp_finalize(float (&colp)[8][2], int staleR, int staleOff,
                                              float* scratch, int tid, int lane,
                                              int warpM, int warpN) {
    __syncthreads();
#pragma unroll
    for (int nt = 0; nt < 8; nt++)
#pragma unroll
        for (int q = 0; q < 2; q++) {
            float p = colp[nt][q];
            p += __shfl_xor_sync(0xffffffffu, p, 4);
            p += __shfl_xor_sync(0xffffffffu, p, 8);
            p += __shfl_xor_sync(0xffffffffu, p, 16);
            colp[nt][q] = p;
        }
    if (lane < 4) {
#pragma unroll
        for (int nt = 0; nt < 8; nt++)
#pragma unroll
            for (int q = 0; q < 2; q++)
                scratch[(warpN * 4 + warpM) * 64 + nt * 8 + lane * 2 + q] = colp[nt][q];
    }
    __syncthreads();
    if (tid < TM) {
        int wn = tid >> 6, cl = tid & 63;
        float s = scratch[(wn * 4 + 0) * 64 + cl] + scratch[(wn * 4 + 1) * 64 + cl]
                + scratch[(wn * 4 + 2) * 64 + cl] + scratch[(wn * 4 + 3) * 64 + cl];
        g_cs[(staleR * 33 + staleOff) * 128 + tid] = s;
    }
#pragma unroll
    for (int nt = 0; nt < 8; nt++) { colp[nt][0] = 0.f; colp[nt][1] = 0.f; }
}

__device__ __forceinline__ void flush_stale(float (&st)[2][8][4], float (&rowp)[2][2],
                                            float (&colp)[8][2], int staleOff, int staleColW,
                                            int staleR0, int staleR, float* scratch,
                                            int tid, int lane, int warpM, int warpN) {
#pragma unroll
    for (int g = 0; g < 16; g += 2)
        stale_pair(g, st, rowp, colp, staleOff, staleColW, staleR0);
    if (staleOff > 0)
        colp_finalize(colp, staleR, staleOff, scratch, tid, lane, warpM, warpN);
}

// one tile: 4 kc MMA blocks into cur; stale epilogue interleaved inside s-loop.
// Exactly ONE stale_pair per s-point (s=3 -> groups kc*4+{0,1}; s=7 -> kc*4+{2,3}).
__device__ __forceinline__ void tile_body(
    float (&cur)[2][8][4], float (&st)[2][8][4],
    float (&rowp)[2][2], float (&colp)[8][2],
    int tIdx, int istart, int nIts,
    int staleOff, int staleColW, int staleR0,
    const __nv_bfloat16* __restrict__ znb,
    uint32_t sB, uint32_t aBase, int aXor, int aC,
    int bRow, int bXor, int bC, int tid)
{
#pragma unroll
    for (int kc = 0; kc < 4; ++kc) {
        const int git = (tIdx - istart) * 4 + kc;
        asm volatile("cp.async.wait_group 1;");
        __syncthreads();
        if (git + 2 < nIts) {
            int r2, o2, c2;
            tmap(istart + ((git + 2) >> 2), r2, o2, c2);
            prefetchB(znb, c2 * TM, (git + 2) & 3, sB + ((git + 2) % 3) * SB_BYTES, tid);
        } else {
            asm volatile("cp.async.commit_group;");
        }
        const uint32_t bufB = sB + (git % 3) * SB_BYTES;
#pragma unroll
        for (int s = 0; s < 8; ++s) {
            // batch ALL fragment loads first: 6 LDSM latencies overlap
            uint32_t af[2][4];
            uint32_t bf[4][4];
#pragma unroll
            for (int mt = 0; mt < 2; mt++)
                ldsm4(af[mt], aBase + mt * 16384 + (((kc * 16 + s * 2 + aC) ^ aXor) << 4));
#pragma unroll
            for (int bg = 0; bg < 4; bg++)
                ldsm4(bf[bg], bufB + (bRow + bg * 16) * 256 + (((s * 2 + bC) ^ bXor) << 4));
            // stale exp work fills the LDSM latency window (one pair per s-point)
            if (staleOff >= 0 && (s & 3) == 3)
                stale_pair(kc * 4 + ((s >> 2) << 1), st, rowp, colp,
                           staleOff, staleColW, staleR0);
#pragma unroll
            for (int bg = 0; bg < 4; bg++)
#pragma unroll
                for (int mt = 0; mt < 2; mt++) {
                    mma_bf16(cur[mt][bg * 2], af[mt], bf[bg]);
                    mma_bf16(cur[mt][bg * 2 + 1], af[mt], bf[bg] + 2);
                }
        }
    }
}

__global__ void __launch_bounds__(256, 1) denom_kernel() {
    extern __shared__ char smem[];
    const int tid = threadIdx.x;
    const int lane = tid & 31;
    const int wid = tid >> 5;
    const int warpM = wid & 3;
    const int warpN = wid >> 2;
    const int cta = blockIdx.x;

    const __nv_bfloat16* __restrict__ znb = g_znb;
    uint32_t sA = smem_u32(smem) + SA_OFF;
    uint32_t sB = smem_u32(smem) + SB_OFF;
    float* scratch = (float*)(smem + SRED_OFF);

    const int aRow = warpM * 32 + (lane & 15);
    const uint32_t aBase = sA + aRow * 1024;
    const int aXor = aRow & 7;
    const int aC = lane >> 4;
    const int bRow = warpN * 64 + (lane & 7) + ((lane >> 4) << 3);
    const int bXor = bRow & 7;
    const int bC = (lane >> 3) & 1;

    const int istart = (cta * NTILES) / NCTA;
    const int iend = ((cta + 1) * NTILES) / NCTA;
    const int nIts = (iend - istart) * 4;

    int rcur, offcur, ccur;
    tmap(istart, rcur, offcur, ccur);
    int rprev = rcur;
    int offFirst = offcur;

    loadA(znb, rcur * TM, sA, tid);
    asm volatile("cp.async.wait_group 0;");
    __syncthreads();
    prefetchB(znb, ccur * TM, 0, sB, tid);
    prefetchB(znb, ccur * TM, 1, sB + SB_BYTES, tid);

    float accA[2][8][4], accB[2][8][4];
#pragma unroll
    for (int mt = 0; mt < 2; mt++)
#pragma unroll
        for (int nt = 0; nt < 8; nt++)
#pragma unroll
            for (int j = 0; j < 4; j++) { accA[mt][nt][j] = 0.f; accB[mt][nt][j] = 0.f; }
    float rowp[2][2] = {{0.f, 0.f}, {0.f, 0.f}};
    float colp[8][2];
#pragma unroll
    for (int nt = 0; nt < 8; nt++) { colp[nt][0] = 0.f; colp[nt][1] = 0.f; }

    int staleOff = -1, staleR = 0, staleColW = 0, staleR0 = 0;

    for (int t = istart; t < iend; ++t) {
        tmap(t, rcur, offcur, ccur);
        const int par = (t - istart) & 1;
        if (rcur != rprev) {
            if (staleOff >= 0) {
                if (par == 0)
                    flush_stale(accB, rowp, colp, staleOff, staleColW, staleR0, staleR,
                                scratch, tid, lane, warpM, warpN);
                else
                    flush_stale(accA, rowp, colp, staleOff, staleColW, staleR0, staleR,
                                scratch, tid, lane, warpM, warpN);
                staleOff = -1;
            }
            emit_rows(rowp, rprev, offFirst, scratch, tid, lane, warpM, warpN);
            rowp[0][0] = rowp[0][1] = rowp[1][0] = rowp[1][1] = 0.f;
            offFirst = offcur;
            asm volatile("cp.async.wait_group 0;");
            __syncthreads();
            loadA(znb, rcur * TM, sA, tid);
            asm volatile("cp.async.wait_group 0;");
            __syncthreads();
            rprev = rcur;
        }

        if (par == 0)
            tile_body(accA, accB, rowp, colp, t, istart, nIts,
                      staleOff, staleColW, staleR0, znb, sB, aBase, aXor, aC,
                      bRow, bXor, bC, tid);
        else
            tile_body(accB, accA, rowp, colp, t, istart, nIts,
                      staleOff, staleColW, staleR0, znb, sB, aBase, aXor, aC,
                      bRow, bXor, bC, tid);

        if (staleOff > 0)
            colp_finalize(colp, staleR, staleOff, scratch, tid, lane, warpM, warpN);

        staleOff = offcur;
        staleR = rcur;
        staleColW = ccur * TM + warpN * 64 + (lane & 3) * 2;
        staleR0 = rcur * TM + warpM * 32 + (lane >> 2);
    }

    const int parEnd = (iend - istart) & 1;
    if (parEnd == 0)
        flush_stale(accB, rowp, colp, staleOff, staleColW, staleR0, staleR,
                    scratch, tid, lane, warpM, warpN);
    else
        flush_stale(accA, rowp, colp, staleOff, staleColW, staleR0, staleR,
                    scratch, tid, lane, warpM, warpN);
    emit_rows(rowp, rprev, offFirst, scratch, tid, lane, warpM, warpN);
}

// ---------------------------------------------------------------------------
// 3) loss + mean
// ---------------------------------------------------------------------------
__global__ void loss_mean_kernel(float* __restrict__ out, int B) {
    __shared__ float wsum[8];
    __shared__ unsigned int sflag;
    int lane = threadIdx.x & 31;
    int wrp = threadIdx.x >> 5;
    int rowg = blockIdx.x * 8 + wrp;
    int N = 2 * B;

    int b = rowg >> 7, lr = rowg & 127;
    float d = g_rs[(b * 33 + lane) * 128 + lr];
    if (lane == 0 && b < 32) d += g_rs[(b * 33 + 32) * 128 + lr];
    {
        int off2 = lane + 1;
        int rr = (b - off2 + 64) & 63;
        if (off2 < 32 || rr < 32) d += g_cs[(rr * 33 + off2) * 128 + lr];
    }
#pragma unroll
    for (int o = 16; o > 0; o >>= 1) d += __shfl_xor_sync(0xffffffffu, d, o);

    if (lane == 0) {
        float pos = g_pos[(rowg < B) ? rowg : (rowg - B)];
        wsum[wrp] = logf(d + 1e-8f) - pos;
    }
    __syncthreads();
    if (threadIdx.x == 0) {
        float s = 0.f;
#pragma unroll
        for (int i = 0; i < 8; i++) s += wsum[i];
        g_bpart[blockIdx.x] = s;
        __threadfence();
        sflag = atomicInc(&g_ctr, NLBLK - 1);
    }
    __syncthreads();
    if (sflag == NLBLK - 1) {
        __shared__ float red[256];
        int t = threadIdx.x;
        const volatile float* bp = g_bpart;
        float s = 0.f;
#pragma unroll
        for (int i = 0; i < NLBLK / 256; i++) s += bp[t + i * 256];
        red[t] = s;
        __syncthreads();
#pragma unroll
        for (int st = 128; st > 0; st >>= 1) {
            if (t < st) red[t] += red[t + st];
            __syncthreads();
        }
        if (t == 0) out[0] = red[0] / (float)N;
    }
}

// ---------------------------------------------------------------------------
extern "C" void kernel_launch(void* const* d_in, const int* in_sizes, int n_in,
                              void* d_out, int out_size) {
    const float* zi = (const float*)d_in[0];
    const float* zj = (const float*)d_in[1];
    int B = in_sizes[0] / D;  // 4096

    cudaFuncSetAttribute(denom_kernel, cudaFuncAttributeMaxDynamicSharedMemorySize, SMEM_TOTAL);

    normalize_kernel<<<B / 8, 256>>>(zi, zj, B);
    denom_kernel<<<NCTA, 256, SMEM_TOTAL>>>();
    loss_mean_kernel<<<NLBLK, 256>>>((float*)d_out, B);
}

// round 15
// speedup vs baseline: 1.0861x; 1.0213x over previous
#include <cuda_runtime.h>
#include <cuda_bf16.h>
#include <math.h>
#include <stdint.h>

// NT-Xent loss. B=4096, D=512. Symmetric fused bf16 HMMA sim-GEMM (R11
// mainloop). Uniform epilogue: every tile emits row+col sums; the diagonal
// exp is subtracted in the loss gather via precomputed |q|^2.

#define D 512
#define MAXN 8192
#define TEMP_INV 2.0f
#define QSCALE 1.6986436f   // sqrt(2 * log2(e))
#define NCTA 148
#define NB 64
#define NTILES 2080

#define TM 128
#define KCHUNK 128

#define SA_OFF 0
#define SA_BYTES (TM * D * 2)
#define SB_OFF SA_BYTES
#define SB_BYTES (TM * KCHUNK * 2)
#define NSTAGE 3
#define SRED_OFF (SB_OFF + NSTAGE * SB_BYTES)
#define SMEM_TOTAL (SRED_OFF + 2048)

#define NLBLK 1024
#define NZR (NB * 33 * 128)

__device__ __nv_bfloat16 g_znb[(size_t)MAXN * D];
__device__ float g_pos[MAXN / 2];
__device__ float g_diag[MAXN];      // |q_row|^2 (exp2 arg of the diagonal)
__device__ float g_rs[NZR];
__device__ float g_cs[NZR];
__device__ float g_bpart[NLBLK];
__device__ unsigned int g_ctr = 0;

__device__ __forceinline__ uint32_t smem_u32(const void* p) {
    uint32_t a;
    asm("{ .reg .u64 t; cvta.to.shared.u64 t, %1; cvt.u32.u64 %0, t; }" : "=r"(a) : "l"(p));
    return a;
}
__device__ __forceinline__ float ex2f(float x) {
    float r;
    asm("ex2.approx.f32 %0, %1;" : "=f"(r) : "f"(x));
    return r;
}
__device__ __forceinline__ void ldsm4(uint32_t* r, uint32_t addr) {
    asm volatile("ldmatrix.sync.aligned.m8n8.x4.shared.b16 {%0,%1,%2,%3}, [%4];"
                 : "=r"(r[0]), "=r"(r[1]), "=r"(r[2]), "=r"(r[3]) : "r"(addr));
}
__device__ __forceinline__ void mma_bf16(float* c, const uint32_t* a, const uint32_t* b) {
    asm volatile(
        "mma.sync.aligned.m16n8k16.row.col.f32.bf16.bf16.f32 "
        "{%0,%1,%2,%3}, {%4,%5,%6,%7}, {%8,%9}, {%0,%1,%2,%3};"
        : "+f"(c[0]), "+f"(c[1]), "+f"(c[2]), "+f"(c[3])
        : "r"(a[0]), "r"(a[1]), "r"(a[2]), "r"(a[3]), "r"(b[0]), "r"(b[1]));
}
__device__ __forceinline__ void tmap(int t, int& r, int& off, int& c) {
    if (t < 32 * 33) { r = t / 33; off = t - r * 33; }
    else { int u = t - 32 * 33; r = 32 + u / 32; off = u - (u / 32) * 32; }
    c = (r + off) & 63;
}

// ---------------------------------------------------------------------------
// 1) normalize: warp per pair. Emits bf16(zn*QSCALE), positives, |q|^2; zeros g_rs.
// ---------------------------------------------------------------------------
__global__ void normalize_kernel(const float* __restrict__ zi,
                                 const float* __restrict__ zj, int B) {
    int lane = threadIdx.x & 31;
    int w = threadIdx.x >> 5;
    int row = blockIdx.x * 8 + w;

    float4 vi[4], vj[4];
    const float4* pi = (const float4*)(zi + (size_t)row * D);
    const float4* pj = (const float4*)(zj + (size_t)row * D);
#pragma unroll
    for (int q = 0; q < 4; q++) { vi[q] = pi[q * 32 + lane]; vj[q] = pj[q * 32 + lane]; }

    float ssi = 0.f, ssj = 0.f, dij = 0.f;
#pragma unroll
    for (int q = 0; q < 4; q++) {
        ssi += vi[q].x * vi[q].x + vi[q].y * vi[q].y + vi[q].z * vi[q].z + vi[q].w * vi[q].w;
        ssj += vj[q].x * vj[q].x + vj[q].y * vj[q].y + vj[q].z * vj[q].z + vj[q].w * vj[q].w;
        dij += vi[q].x * vj[q].x + vi[q].y * vj[q].y + vi[q].z * vj[q].z + vi[q].w * vj[q].w;
    }
#pragma unroll
    for (int o = 16; o > 0; o >>= 1) {
        ssi += __shfl_xor_sync(0xffffffffu, ssi, o);
        ssj += __shfl_xor_sync(0xffffffffu, ssj, o);
        dij += __shfl_xor_sync(0xffffffffu, dij, o);
    }
    float ri = rsqrtf(ssi), rj = rsqrtf(ssj);
    float sci = ri * QSCALE, scj = rj * QSCALE;

    __nv_bfloat16* oi = g_znb + (size_t)row * D;
    __nv_bfloat16* oj = g_znb + (size_t)(row + B) * D;
    float qsi = 0.f, qsj = 0.f;   // |q|^2 of the quantized rows
#pragma unroll
    for (int q = 0; q < 4; q++) {
        int e = (q * 32 + lane) * 4;
        __nv_bfloat162 a0 = __floats2bfloat162_rn(vi[q].x * sci, vi[q].y * sci);
        __nv_bfloat162 a1 = __floats2bfloat162_rn(vi[q].z * sci, vi[q].w * sci);
        *(__nv_bfloat162*)(oi + e) = a0;
        *(__nv_bfloat162*)(oi + e + 2) = a1;
        __nv_bfloat162 b0 = __floats2bfloat162_rn(vj[q].x * scj, vj[q].y * scj);
        __nv_bfloat162 b1 = __floats2bfloat162_rn(vj[q].z * scj, vj[q].w * scj);
        *(__nv_bfloat162*)(oj + e) = b0;
        *(__nv_bfloat162*)(oj + e + 2) = b1;
        float2 f;
        f = __bfloat1622float2(a0); qsi += f.x * f.x + f.y * f.y;
        f = __bfloat1622float2(a1); qsi += f.x * f.x + f.y * f.y;
        f = __bfloat1622float2(b0); qsj += f.x * f.x + f.y * f.y;
        f = __bfloat1622float2(b1); qsj += f.x * f.x + f.y * f.y;
    }
#pragma unroll
    for (int o = 16; o > 0; o >>= 1) {
        qsi += __shfl_xor_sync(0xffffffffu, qsi, o);
        qsj += __shfl_xor_sync(0xffffffffu, qsj, o);
    }
    if (lane == 0) {
        g_pos[row] = dij * ri * rj * TEMP_INV;
        g_diag[row] = qsi;
        g_diag[row + B] = qsj;
    }
    for (int i = blockIdx.x * blockDim.x + threadIdx.x; i < NZR; i += gridDim.x * blockDim.x)
        g_rs[i] = 0.0f;
}

// ---------------------------------------------------------------------------
// 2) denom helpers
// ---------------------------------------------------------------------------
__device__ __forceinline__ void prefetchB(const __nv_bfloat16* __restrict__ znb,
                                          int colBase, int kc, uint32_t smemBuf, int tid) {
#pragma unroll
    for (int i = 0; i < 8; i++) {
        int idx = tid + i * 256;
        int n = idx >> 4;
        int c = idx & 15;
        const void* g = znb + (size_t)(colBase + n) * D + kc * KCHUNK + c * 8;
        uint32_t s = smemBuf + n * 256 + ((c ^ (n & 7)) << 4);
        asm volatile("cp.async.cg.shared.global [%0], [%1], 16;" :: "r"(s), "l"(g));
    }
    asm volatile("cp.async.commit_group;");
}
__device__ __forceinline__ void loadA(const __nv_bfloat16* __restrict__ znb,
                                      int rowBase, uint32_t sA, int tid) {
#pragma unroll 8
    for (int idx = tid; idx < TM * 64; idx += 256) {
        int r = idx >> 6;
        int c = idx & 63;
        const void* g = znb + (size_t)(rowBase + r) * D + c * 8;
        uint32_t s = sA + r * 1024 + ((c ^ (r & 7)) << 4);
        asm volatile("cp.async.cg.shared.global [%0], [%1], 16;" :: "r"(s), "l"(g));
    }
    asm volatile("cp.async.commit_group;");
}

__device__ __forceinline__ void emit_rows(float rowp[2][2], int r, int offFirst,
                                          float* scratch, int tid, int lane,
                                          int warpM, int warpN) {
    __syncthreads();
#pragma unroll
    for (int mt = 0; mt < 2; mt++)
#pragma unroll
        for (int h = 0; h < 2; h++) {
            float p = rowp[mt][h];
            p += __shfl_xor_sync(0xffffffffu, p, 1);
            p += __shfl_xor_sync(0xffffffffu, p, 2);
            rowp[mt][h] = p;
        }
    if ((lane & 3) == 0) {
#pragma unroll
        for (int mt = 0; mt < 2; mt++)
#pragma unroll
            for (int h = 0; h < 2; h++) {
                int rl = warpM * 32 + mt * 16 + (lane >> 2) + 8 * h;
                scratch[rl * 2 + warpN] = rowp[mt][h];
            }
    }
    __syncthreads();
    if (tid < TM)
        g_rs[(r * 33 + offFirst) * 128 + tid] = scratch[tid * 2] + scratch[tid * 2 + 1];
}

// uniform epilogue: 4 groups [g0, g0+4) -> row + col partials (no diag mask)
__device__ __forceinline__ void stale_groups(int g0, float (&st)[2][8][4],
                                             float (&rowp)[2][2], float (&colp)[8][2]) {
#pragma unroll
    for (int u = 0; u < 4; u++) {
        const int g = g0 + u;
        const int mt = g >> 3, nt = g & 7;
        float e0 = ex2f(st[mt][nt][0]);
        float e1 = ex2f(st[mt][nt][1]);
        float e2 = ex2f(st[mt][nt][2]);
        float e3 = ex2f(st[mt][nt][3]);
        rowp[mt][0] += e0 + e1;
        rowp[mt][1] += e2 + e3;
        colp[nt][0] += e0 + e2;
        colp[nt][1] += e1 + e3;
        st[mt][nt][0] = 0.f; st[mt][nt][1] = 0.f;
        st[mt][nt][2] = 0.f; st[mt][nt][3] = 0.f;
    }
}

__device__ __forceinline__ void colp_finalize(float (&colp)[8][2], int staleR, int staleOff,
                                              float* scratch, int tid, int lane,
                                              int warpM, int warpN) {
    __syncthreads();
#pragma unroll
    for (int nt = 0; nt < 8; nt++)
#pragma unroll
        for (int q = 0; q < 2; q++) {
            float p = colp[nt][q];
            p += __shfl_xor_sync(0xffffffffu, p, 4);
            p += __shfl_xor_sync(0xffffffffu, p, 8);
            p += __shfl_xor_sync(0xffffffffu, p, 16);
            colp[nt][q] = p;
        }
    if (lane < 4) {
#pragma unroll
        for (int nt = 0; nt < 8; nt++)
#pragma unroll
            for (int q = 0; q < 2; q++)
                scratch[(warpN * 4 + warpM) * 64 + nt * 8 + lane * 2 + q] = colp[nt][q];
    }
    __syncthreads();
    if (tid < TM) {
        int wn = tid >> 6, cl = tid & 63;
        float s = scratch[(wn * 4 + 0) * 64 + cl] + scratch[(wn * 4 + 1) * 64 + cl]
                + scratch[(wn * 4 + 2) * 64 + cl] + scratch[(wn * 4 + 3) * 64 + cl];
        g_cs[(staleR * 33 + staleOff) * 128 + tid] = s;   // off=0 slot unused by gather
    }
#pragma unroll
    for (int nt = 0; nt < 8; nt++) { colp[nt][0] = 0.f; colp[nt][1] = 0.f; }
}

__device__ __forceinline__ void flush_stale(float (&st)[2][8][4], float (&rowp)[2][2],
                                            float (&colp)[8][2], int staleOff, int staleR,
                                            float* scratch, int tid, int lane,
                                            int warpM, int warpN) {
    stale_groups(0, st, rowp, colp);
    stale_groups(4, st, rowp, colp);
    stale_groups(8, st, rowp, colp);
    stale_groups(12, st, rowp, colp);
    colp_finalize(colp, staleR, staleOff, scratch, tid, lane, warpM, warpN);
}

// one tile (R11 scheduling): 4 kc MMA blocks into cur, each followed by a
// quarter of the stale epilogue
__device__ __forceinline__ void tile_body(
    float (&cur)[2][8][4], float (&st)[2][8][4],
    float (&rowp)[2][2], float (&colp)[8][2],
    int tIdx, int istart, int nIts, int haveStale,
    const __nv_bfloat16* __restrict__ znb,
    uint32_t sB, uint32_t aBase, int aXor, int aC,
    int bRow, int bXor, int bC, int tid)
{
#pragma unroll
    for (int kc = 0; kc < 4; ++kc) {
        const int git = (tIdx - istart) * 4 + kc;
        asm volatile("cp.async.wait_group 1;");
        __syncthreads();
        if (git + 2 < nIts) {
            int r2, o2, c2;
            tmap(istart + ((git + 2) >> 2), r2, o2, c2);
            prefetchB(znb, c2 * TM, (git + 2) & 3, sB + ((git + 2) % 3) * SB_BYTES, tid);
        } else {
            asm volatile("cp.async.commit_group;");
        }
        const uint32_t bufB = sB + (git % 3) * SB_BYTES;
#pragma unroll
        for (int s = 0; s < 8; ++s) {
            uint32_t af[2][4];
#pragma unroll
            for (int mt = 0; mt < 2; mt++)
                ldsm4(af[mt], aBase + mt * 16384 + (((kc * 16 + s * 2 + aC) ^ aXor) << 4));
#pragma unroll
            for (int bg = 0; bg < 4; bg++) {
                uint32_t bf[4];
                ldsm4(bf, bufB + (bRow + bg * 16) * 256 + (((s * 2 + bC) ^ bXor) << 4));
#pragma unroll
                for (int mt = 0; mt < 2; mt++) {
                    mma_bf16(cur[mt][bg * 2], af[mt], bf);
                    mma_bf16(cur[mt][bg * 2 + 1], af[mt], bf + 2);
                }
            }
        }
        if (haveStale)
            stale_groups(kc * 4, st, rowp, colp);
    }
}

__global__ void __launch_bounds__(256, 1) denom_kernel() {
    extern __shared__ char smem[];
    const int tid = threadIdx.x;
    const int lane = tid & 31;
    const int wid = tid >> 5;
    const int warpM = wid & 3;
    const int warpN = wid >> 2;
    const int cta = blockIdx.x;

    const __nv_bfloat16* __restrict__ znb = g_znb;
    uint32_t sA = smem_u32(smem) + SA_OFF;
    uint32_t sB = smem_u32(smem) + SB_OFF;
    float* scratch = (float*)(smem + SRED_OFF);

    const int aRow = warpM * 32 + (lane & 15);
    const uint32_t aBase = sA + aRow * 1024;
    const int aXor = aRow & 7;
    const int aC = lane >> 4;
    const int bRow = warpN * 64 + (lane & 7) + ((lane >> 4) << 3);
    const int bXor = bRow & 7;
    const int bC = (lane >> 3) & 1;

    const int istart = (cta * NTILES) / NCTA;
    const int iend = ((cta + 1) * NTILES) / NCTA;
    const int nIts = (iend - istart) * 4;

    int rcur, offcur, ccur;
    tmap(istart, rcur, offcur, ccur);
    int rprev = rcur;
    int offFirst = offcur;

    loadA(znb, rcur * TM, sA, tid);
    asm volatile("cp.async.wait_group 0;");
    __syncthreads();
    prefetchB(znb, ccur * TM, 0, sB, tid);
    prefetchB(znb, ccur * TM, 1, sB + SB_BYTES, tid);

    float accA[2][8][4], accB[2][8][4];
#pragma unroll
    for (int mt = 0; mt < 2; mt++)
#pragma unroll
        for (int nt = 0; nt < 8; nt++)
#pragma unroll
            for (int j = 0; j < 4; j++) { accA[mt][nt][j] = 0.f; accB[mt][nt][j] = 0.f; }
    float rowp[2][2] = {{0.f, 0.f}, {0.f, 0.f}};
    float colp[8][2];
#pragma unroll
    for (int nt = 0; nt < 8; nt++) { colp[nt][0] = 0.f; colp[nt][1] = 0.f; }

    int staleOff = -1, staleR = 0;

    for (int t = istart; t < iend; ++t) {
        tmap(t, rcur, offcur, ccur);
        const int par = (t - istart) & 1;
        if (rcur != rprev) {
            if (staleOff >= 0) {
                if (par == 0)
                    flush_stale(accB, rowp, colp, staleOff, staleR, scratch, tid, lane, warpM, warpN);
                else
                    flush_stale(accA, rowp, colp, staleOff, staleR, scratch, tid, lane, warpM, warpN);
                staleOff = -1;
            }
            emit_rows(rowp, rprev, offFirst, scratch, tid, lane, warpM, warpN);
            rowp[0][0] = rowp[0][1] = rowp[1][0] = rowp[1][1] = 0.f;
            offFirst = offcur;
            asm volatile("cp.async.wait_group 0;");
            __syncthreads();
            loadA(znb, rcur * TM, sA, tid);
            asm volatile("cp.async.wait_group 0;");
            __syncthreads();
            rprev = rcur;
        }

        if (par == 0)
            tile_body(accA, accB, rowp, colp, t, istart, nIts, staleOff >= 0,
                      znb, sB, aBase, aXor, aC, bRow, bXor, bC, tid);
        else
            tile_body(accB, accA, rowp, colp, t, istart, nIts, staleOff >= 0,
                      znb, sB, aBase, aXor, aC, bRow, bXor, bC, tid);

        if (staleOff >= 0)
            colp_finalize(colp, staleR, staleOff, scratch, tid, lane, warpM, warpN);

        staleOff = offcur;
        staleR = rcur;
    }

    const int parEnd = (iend - istart) & 1;
    if (parEnd == 0)
        flush_stale(accB, rowp, colp, staleOff, staleR, scratch, tid, lane, warpM, warpN);
    else
        flush_stale(accA, rowp, colp, staleOff, staleR, scratch, tid, lane, warpM, warpN);
    emit_rows(rowp, rprev, offFirst, scratch, tid, lane, warpM, warpN);
}

// ---------------------------------------------------------------------------
// 3) loss + mean (diagonal exp subtracted via g_diag)
// ---------------------------------------------------------------------------
__global__ void loss_mean_kernel(float* __restrict__ out, int B) {
    __shared__ float wsum[8];
    __shared__ unsigned int sflag;
    int lane = threadIdx.x & 31;
    int wrp = threadIdx.x >> 5;
    int rowg = blockIdx.x * 8 + wrp;
    int N = 2 * B;

    int b = rowg >> 7, lr = rowg & 127;
    float d = g_rs[(b * 33 + lane) * 128 + lr];
    if (lane == 0 && b < 32) d += g_rs[(b * 33 + 32) * 128 + lr];
    {
        int off2 = lane + 1;
        int rr = (b - off2 + 64) & 63;
        if (off2 < 32 || rr < 32) d += g_cs[(rr * 33 + off2) * 128 + lr];
    }
#pragma unroll
    for (int o = 16; o > 0; o >>= 1) d += __shfl_xor_sync(0xffffffffu, d, o);

    if (lane == 0) {
        d -= ex2f(g_diag[rowg]);              // remove self-similarity term
        float pos = g_pos[(rowg < B) ? rowg : (rowg - B)];
        wsum[wrp] = logf(d + 1e-8f) - pos;
    }
    __syncthreads();
    if (threadIdx.x == 0) {
        float s = 0.f;
#pragma unroll
        for (int i = 0; i < 8; i++) s += wsum[i];
        g_bpart[blockIdx.x] = s;
        __threadfence();
        sflag = atomicInc(&g_ctr, NLBLK - 1);
    }
    __syncthreads();
    if (sflag == NLBLK - 1) {
        __shared__ float red[256];
        int t = threadIdx.x;
        const volatile float* bp = g_bpart;
        float s = 0.f;
#pragma unroll
        for (int i = 0; i < NLBLK / 256; i++) s += bp[t + i * 256];
        red[t] = s;
        __syncthreads();
#pragma unroll
        for (int st = 128; st > 0; st >>= 1) {
            if (t < st) red[t] += red[t + st];
            __syncthreads();
        }
        if (t == 0) out[0] = red[0] / (float)N;
    }
}

// ---------------------------------------------------------------------------
extern "C" void kernel_launch(void* const* d_in, const int* in_sizes, int n_in,
                              void* d_out, int out_size) {
    const float* zi = (const float*)d_in[0];
    const float* zj = (const float*)d_in[1];
    int B = in_sizes[0] / D;  // 4096

    cudaFuncSetAttribute(denom_kernel, cudaFuncAttributeMaxDynamicSharedMemorySize, SMEM_TOTAL);

    normalize_kernel<<<B / 8, 256>>>(zi, zj, B);
    denom_kernel<<<NCTA, 256, SMEM_TOTAL>>>();
    loss_mean_kernel<<<NLBLK, 256>>>((float*)d_out, B);
}